// round 15
// baseline (speedup 1.0000x reference)
#include <cuda_runtime.h>
#include <cuda_fp16.h>
#include <cuda_bf16.h>
#include <cstdint>
#include <math.h>

#define BH   32
#define LEN  4096
#define DIM  64
#define MF   64
#define CHK  128
#define NC   (LEN/CHK)     // 32

#define DN     0.35355339059327373f  // 64^-0.25
#define RATIO  0.125f                // 64^-0.5
#define EPSV   1e-4f
#define QSCALE 256.0f                // common q-feature scale (cancels in ratio)

// Scratch (device globals: allocation-free rule)
__device__ __half         g_qp[BH*LEN*MF];   // q features * 256, fp16 (tf32-lossless)
__device__ __nv_bfloat16  g_kp[BH*LEN*MF];   // t = exp(dash - diag), bf16
__device__ float g_bhmax[BH];
__device__ float g_kvt[BH*NC*MF*DIM];        // per-chunk sum t_j*v_j -> excl prefix
__device__ float g_ts[BH*NC*MF];             // per-chunk sum t_j -> excl prefix
__device__ float g_vs[BH*NC*DIM];            // per-chunk sum v_j -> excl prefix

// ==================== helpers ====================

__device__ __forceinline__ void atomicMaxFloat(float* addr, float val) {
    int* ia = (int*)addr;
    int old = *ia;
    while (__int_as_float(old) < val) {
        int assumed = old;
        old = atomicCAS(ia, assumed, __float_as_int(val));
        if (old == assumed) break;
    }
}

__device__ __forceinline__ uint32_t tf32c(float f) {
    uint32_t r; asm("cvt.rna.tf32.f32 %0, %1;" : "=r"(r) : "f"(f)); return r;
}
__device__ __forceinline__ void tf32split(float f, uint32_t& hi, uint32_t& lo) {
    hi = tf32c(f);
    lo = tf32c(f - __uint_as_float(hi));
}
__device__ __forceinline__ float bf16lo(uint32_t u) { return __uint_as_float(u << 16); }
__device__ __forceinline__ float bf16hi(uint32_t u) { return __uint_as_float(u & 0xFFFF0000u); }

// mma.sync m16n8k8 tf32: D += A*B
__device__ __forceinline__ void mma1688(float* d, const uint32_t* a, uint32_t b0, uint32_t b1) {
    asm volatile(
        "mma.sync.aligned.m16n8k8.row.col.f32.tf32.tf32.f32 "
        "{%0,%1,%2,%3}, {%4,%5,%6,%7}, {%8,%9}, {%0,%1,%2,%3};"
        : "+f"(d[0]), "+f"(d[1]), "+f"(d[2]), "+f"(d[3])
        : "r"(a[0]), "r"(a[1]), "r"(a[2]), "r"(a[3]), "r"(b0), "r"(b1));
}

// ---------------------------------------------------------------------------
// Feature kernel (split-tf32 mma). 128 rows = one chunk per block, 256 thr.
// ---------------------------------------------------------------------------
#define FEATQ_SMEM (128*68*4 + 2*64*68*4)              // 69632
#define FEATK_SMEM (FEATQ_SMEM + 64*133*4)             // 103680

template<bool IS_Q>
__global__ void __launch_bounds__(256, 2)
feat_kernel(const float* __restrict__ x, const float* __restrict__ proj,
            const float* __restrict__ v) {
    extern __shared__ char fsm[];
    float*    Xs  = (float*)fsm;                       // [row][d] (x * DN)
    uint32_t* Ph  = (uint32_t*)(fsm + 128*68*4);       // [m][d] hi
    uint32_t* Pl  = Ph + 64*68;                        // [m][d] lo
    uint32_t* VsT = (uint32_t*)(fsm + FEATQ_SMEM);     // [d][j] tf32 (K only)
    uint32_t* tS  = (uint32_t*)fsm;                    // [m][j] tf32, aliases Xs (K only)

    const int tid = threadIdx.x, wid = tid >> 5, lane = tid & 31;
    const int g = lane >> 2, t = lane & 3;
    const int rowBase = blockIdx.x * 128;
    const int bh = blockIdx.x >> 5;

    if (IS_Q && blockIdx.x == 0 && tid < BH) g_bhmax[tid] = -INFINITY;

    for (int i4 = tid; i4 < 1024; i4 += 256) {
        float4 p = ((const float4*)proj)[i4];
        const int d = i4 >> 4, m0 = (i4 & 15) * 4;
        tf32split(p.x, Ph[(m0+0)*68 + d], Pl[(m0+0)*68 + d]);
        tf32split(p.y, Ph[(m0+1)*68 + d], Pl[(m0+1)*68 + d]);
        tf32split(p.z, Ph[(m0+2)*68 + d], Pl[(m0+2)*68 + d]);
        tf32split(p.w, Ph[(m0+3)*68 + d], Pl[(m0+3)*68 + d]);
    }
    {
        const float4* xg = (const float4*)(x + (size_t)rowBase * DIM);
        const float4* vg = (const float4*)(v + (size_t)rowBase * DIM);
        for (int i4 = tid; i4 < 2048; i4 += 256) {
            const int r = i4 >> 4, d0 = (i4 & 15) * 4;
            float4 xv = xg[i4];
            Xs[r*68 + d0 + 0] = xv.x * DN;
            Xs[r*68 + d0 + 1] = xv.y * DN;
            Xs[r*68 + d0 + 2] = xv.z * DN;
            Xs[r*68 + d0 + 3] = xv.w * DN;
            if (!IS_Q) {
                float4 v4 = vg[i4];
                VsT[(d0+0)*133 + r] = tf32c(v4.x);
                VsT[(d0+1)*133 + r] = tf32c(v4.y);
                VsT[(d0+2)*133 + r] = tf32c(v4.z);
                VsT[(d0+3)*133 + r] = tf32c(v4.w);
            }
        }
    }
    __syncthreads();

    const int r0 = wid * 16;
    const int ra = r0 + g, rb = ra + 8;

    float dga = 0.f, dgb = 0.f;
    #pragma unroll
    for (int dd = 0; dd < 16; ++dd) {
        const int d = t*16 + dd;
        const float xa = Xs[ra*68 + d], xb = Xs[rb*68 + d];
        dga += xa*xa; dgb += xb*xb;
    }
    dga += __shfl_xor_sync(0xffffffffu, dga, 1);
    dga += __shfl_xor_sync(0xffffffffu, dga, 2);
    dgb += __shfl_xor_sync(0xffffffffu, dgb, 1);
    dgb += __shfl_xor_sync(0xffffffffu, dgb, 2);
    dga *= 0.5f;
    dgb *= 0.5f;

    uint32_t ah[8][4], al[8][4];
    #pragma unroll
    for (int k = 0; k < 8; ++k) {
        tf32split(Xs[ra*68 + k*8 + t],     ah[k][0], al[k][0]);
        tf32split(Xs[rb*68 + k*8 + t],     ah[k][1], al[k][1]);
        tf32split(Xs[ra*68 + k*8 + t + 4], ah[k][2], al[k][2]);
        tf32split(Xs[rb*68 + k*8 + t + 4], ah[k][3], al[k][3]);
    }
    if (!IS_Q) __syncthreads();   // all warps done reading Xs before tS overwrites it

    float D[8][4] = {};
    #pragma unroll
    for (int n0 = 0; n0 < 8; ++n0) {
        const int nrow = n0*8 + g;
        #pragma unroll
        for (int k = 0; k < 8; ++k) {
            const uint32_t bh0 = Ph[nrow*68 + k*8 + t];
            const uint32_t bh1 = Ph[nrow*68 + k*8 + t + 4];
            const uint32_t bl0 = Pl[nrow*68 + k*8 + t];
            const uint32_t bl1 = Pl[nrow*68 + k*8 + t + 4];
            mma1688(D[n0], ah[k], bh0, bh1);
            mma1688(D[n0], ah[k], bl0, bl1);
            mma1688(D[n0], al[k], bh0, bh1);
        }
    }

    if (IS_Q) {
        float mxa = -INFINITY, mxb = -INFINITY;
        #pragma unroll
        for (int n0 = 0; n0 < 8; ++n0) {
            mxa = fmaxf(mxa, fmaxf(D[n0][0], D[n0][1]));
            mxb = fmaxf(mxb, fmaxf(D[n0][2], D[n0][3]));
        }
        mxa = fmaxf(mxa, __shfl_xor_sync(0xffffffffu, mxa, 1));
        mxa = fmaxf(mxa, __shfl_xor_sync(0xffffffffu, mxa, 2));
        mxb = fmaxf(mxb, __shfl_xor_sync(0xffffffffu, mxb, 1));
        mxb = fmaxf(mxb, __shfl_xor_sync(0xffffffffu, mxb, 2));
        const float suba = dga + mxa, subb = dgb + mxb;
        __half* qa = g_qp + (size_t)(rowBase + ra)*MF;
        __half* qb = g_qp + (size_t)(rowBase + rb)*MF;
        const float QR = QSCALE * RATIO;
        #pragma unroll
        for (int n0 = 0; n0 < 8; ++n0) {
            *(__half2*)&qa[n0*8 + 2*t] = __floats2half2_rn(
                QR * (__expf(D[n0][0] - suba) + EPSV),
                QR * (__expf(D[n0][1] - suba) + EPSV));
            *(__half2*)&qb[n0*8 + 2*t] = __floats2half2_rn(
                QR * (__expf(D[n0][2] - subb) + EPSV),
                QR * (__expf(D[n0][3] - subb) + EPSV));
        }
    } else {
        float bm = -INFINITY;
        __nv_bfloat16* ka = g_kp + (size_t)(rowBase + ra)*MF;
        __nv_bfloat16* kb = g_kp + (size_t)(rowBase + rb)*MF;
        #pragma unroll
        for (int n0 = 0; n0 < 8; ++n0) {
            bm = fmaxf(bm, fmaxf(fmaxf(D[n0][0], D[n0][1]), fmaxf(D[n0][2], D[n0][3])));
            const float t0 = __expf(D[n0][0] - dga), t1 = __expf(D[n0][1] - dga);
            const float t2 = __expf(D[n0][2] - dgb), t3 = __expf(D[n0][3] - dgb);
            *(__nv_bfloat162*)&ka[n0*8 + 2*t] = __floats2bfloat162_rn(t0, t1);
            *(__nv_bfloat162*)&kb[n0*8 + 2*t] = __floats2bfloat162_rn(t2, t3);
            const int m0 = n0*8 + 2*t;
            tS[(m0  )*133 + ra] = tf32c(t0);
            tS[(m0+1)*133 + ra] = tf32c(t1);
            tS[(m0  )*133 + rb] = tf32c(t2);
            tS[(m0+1)*133 + rb] = tf32c(t3);
        }
        #pragma unroll
        for (int off = 16; off; off >>= 1)
            bm = fmaxf(bm, __shfl_xor_sync(0xffffffffu, bm, off));
        if (lane == 0) atomicMaxFloat(&g_bhmax[bh], bm);
        __syncthreads();

        // fused chunk-state phase: kvt = V^T @ t, row sums
        const int dw = wid >> 1, nw = wid & 1;
        const int da = dw*16 + g, db = da + 8;
        float D4[4][4] = {};
        #pragma unroll
        for (int kt = 0; kt < 16; ++kt) {
            uint32_t a[4];
            a[0] = VsT[da*133 + kt*8 + t];
            a[1] = VsT[db*133 + kt*8 + t];
            a[2] = VsT[da*133 + kt*8 + t + 4];
            a[3] = VsT[db*133 + kt*8 + t + 4];
            #pragma unroll
            for (int n0 = 0; n0 < 4; ++n0) {
                const int mrow = nw*32 + n0*8 + g;
                mma1688(D4[n0], a, tS[mrow*133 + kt*8 + t], tS[mrow*133 + kt*8 + t + 4]);
            }
        }
        float* kvb = g_kvt + (size_t)blockIdx.x * MF * DIM;
        #pragma unroll
        for (int n0 = 0; n0 < 4; ++n0) {
            const int m = nw*32 + n0*8 + 2*t;
            *(float2*)&kvb[da*MF + m] = make_float2(D4[n0][0], D4[n0][1]);
            *(float2*)&kvb[db*MF + m] = make_float2(D4[n0][2], D4[n0][3]);
        }
        if (tid < 64) {
            float s = 0.f;
            #pragma unroll 8
            for (int j = 0; j < CHK; ++j) s += __uint_as_float(tS[tid*133 + j]);
            g_ts[(size_t)blockIdx.x * MF + tid] = s;
        } else if (tid < 128) {
            const int d = tid - 64;
            float s = 0.f;
            #pragma unroll 8
            for (int j = 0; j < CHK; ++j) s += __uint_as_float(VsT[d*133 + j]);
            g_vs[(size_t)blockIdx.x * DIM + d] = s;
        }
    }
}

// ---------------------------------------------------------------------------
// Exclusive prefix over 32 chunks (batched MLP=32).
// ---------------------------------------------------------------------------
__global__ void scan_kernel() {
    const int tid = threadIdx.x;
    float* p;
    size_t stride;
    if (blockIdx.x < 512) {
        const int gid = blockIdx.x * 256 + tid;
        p = g_kvt + (size_t)(gid >> 12)*NC*MF*DIM + (gid & 4095);
        stride = MF*DIM;
    } else if (blockIdx.x < 520) {
        const int lid = (blockIdx.x - 512) * 256 + tid;
        p = g_ts + (size_t)(lid >> 6)*NC*MF + (lid & 63);
        stride = MF;
    } else {
        const int lid = (blockIdx.x - 520) * 256 + tid;
        p = g_vs + (size_t)(lid >> 6)*NC*DIM + (lid & 63);
        stride = DIM;
    }
    float vals[NC];
    #pragma unroll
    for (int c = 0; c < NC; ++c) vals[c] = p[(size_t)c*stride];
    float run = 0.f;
    #pragma unroll
    for (int c = 0; c < NC; ++c) { const float tv = vals[c]; vals[c] = run; run += tv; }
    #pragma unroll
    for (int c = 0; c < NC; ++c) p[(size_t)c*stride] = vals[c];
}

// ---------------------------------------------------------------------------
// attn: fused S->SV via in-register fragment conversion, 2 CTAs/SM.
// Q features fp16 (x256, cancels in ratio); k features bf16.
// ---------------------------------------------------------------------------
#define KS_OFF   0
#define VS_OFF   34816
#define KVT_OFF  69632
#define KSUM_OFF 87040
#define VSP_OFF  87296
#define ATTN_SMEM 87552

__global__ void __launch_bounds__(256, 2)
attn_kernel(const float* __restrict__ v, float* __restrict__ out) {
    extern __shared__ char smem[];
    uint32_t* Ks   = (uint32_t*)(smem + KS_OFF);
    uint32_t* Vs   = (uint32_t*)(smem + VS_OFF);
    uint32_t* KVT  = (uint32_t*)(smem + KVT_OFF);
    float*    ksum = (float*)(smem + KSUM_OFF);
    float*    vsP  = (float*)(smem + VSP_OFF);

    const int tid = threadIdx.x, wid = tid >> 5, lane = tid & 31;
    const int g = lane >> 2, t = lane & 3;
    const int bh = blockIdx.x >> 5, c = blockIdx.x & 31;
    const size_t tokBase = (size_t)blockIdx.x * CHK;
    const float cr = RATIO * __expf(-g_bhmax[bh]);
    const float er = RATIO * EPSV;

    const int PERM[8] = {0, 1, 2, 3, 7, 6, 5, 4};
    const int r0 = PERM[wid] * 16;
    const int ra = r0 + g, rb = ra + 8;

    // Q fragments straight from gmem (fp16; half->float is tf32-exact)
    uint32_t qa[8][4];
    {
        const __half* qrow_a = g_qp + (tokBase + ra)*MF;
        const __half* qrow_b = g_qp + (tokBase + rb)*MF;
        #pragma unroll
        for (int k = 0; k < 8; ++k) {
            qa[k][0] = __float_as_uint(__half2float(qrow_a[k*8 + t]));
            qa[k][1] = __float_as_uint(__half2float(qrow_b[k*8 + t]));
            qa[k][2] = __float_as_uint(__half2float(qrow_a[k*8 + t + 4]));
            qa[k][3] = __float_as_uint(__half2float(qrow_b[k*8 + t + 4]));
        }
    }

    const uint4*  kpp = (const uint4*)(g_kp + tokBase*MF);   // 8 bf16 per uint4
    const float4* vpp = (const float4*)(v    + tokBase*DIM);
    const float4* kvp = (const float4*)(g_kvt + (size_t)blockIdx.x*MF*DIM);

    for (int i8 = tid; i8 < 1024; i8 += 256) {
        const int r = i8 >> 3, c0 = (i8 & 7) * 8;
        uint4 kd = kpp[i8];
        Ks[r*68 + c0 + 0] = tf32c(fmaf(bf16lo(kd.x), cr, er));
        Ks[r*68 + c0 + 1] = tf32c(fmaf(bf16hi(kd.x), cr, er));
        Ks[r*68 + c0 + 2] = tf32c(fmaf(bf16lo(kd.y), cr, er));
        Ks[r*68 + c0 + 3] = tf32c(fmaf(bf16hi(kd.y), cr, er));
        Ks[r*68 + c0 + 4] = tf32c(fmaf(bf16lo(kd.z), cr, er));
        Ks[r*68 + c0 + 5] = tf32c(fmaf(bf16hi(kd.z), cr, er));
        Ks[r*68 + c0 + 6] = tf32c(fmaf(bf16lo(kd.w), cr, er));
        Ks[r*68 + c0 + 7] = tf32c(fmaf(bf16hi(kd.w), cr, er));
    }
    for (int i4 = tid; i4 < 2048; i4 += 256) {
        const int r = i4 >> 4, c0 = (i4 & 15) * 4;
        float4 v4 = vpp[i4];
        Vs[r*68 + c0 + 0] = tf32c(v4.x);
        Vs[r*68 + c0 + 1] = tf32c(v4.y);
        Vs[r*68 + c0 + 2] = tf32c(v4.z);
        Vs[r*68 + c0 + 3] = tf32c(v4.w);
    }
    for (int i4 = tid; i4 < 1024; i4 += 256) {
        const int d = i4 >> 4, m0 = (i4 & 15) * 4;
        float4 kv4 = kvp[i4];
        KVT[d*68 + m0 + 0] = tf32c(cr * kv4.x);
        KVT[d*68 + m0 + 1] = tf32c(cr * kv4.y);
        KVT[d*68 + m0 + 2] = tf32c(cr * kv4.z);
        KVT[d*68 + m0 + 3] = tf32c(cr * kv4.w);
    }
    if (tid < 64) ksum[tid] = fmaf(cr, g_ts[(size_t)blockIdx.x*MF + tid], er * (128.f * c));
    else if (tid < 128) vsP[tid - 64] = g_vs[(size_t)blockIdx.x*DIM + (tid - 64)];
    __syncthreads();

    // denominator part 2 + row feature-sums from registers (all x256, consistent)
    float rs0 = 0.f, rs1 = 0.f, qs0 = 0.f, qs1 = 0.f;
    #pragma unroll
    for (int k = 0; k < 8; ++k) {
        const float q0 = __uint_as_float(qa[k][0]), q2 = __uint_as_float(qa[k][2]);
        const float q1 = __uint_as_float(qa[k][1]), q3 = __uint_as_float(qa[k][3]);
        rs0 += q0 * ksum[k*8 + t] + q2 * ksum[k*8 + t + 4];
        rs1 += q1 * ksum[k*8 + t] + q3 * ksum[k*8 + t + 4];
        qs0 += q0 + q2;
        qs1 += q1 + q3;
    }

    float D[8][4] = {};
    // inter: D = Q @ (cr * KVT_prev)^T
    #pragma unroll
    for (int n0 = 0; n0 < 8; ++n0) {
        const int drow = n0*8 + g;
        #pragma unroll
        for (int k = 0; k < 8; ++k)
            mma1688(D[n0], qa[k], KVT[drow*68 + k*8 + t], KVT[drow*68 + k*8 + t + 4]);
    }

    // fused S -> SV per causal k-tile; S never hits smem.
    const int src1 = (g << 2) + (t >> 1);
    const int src2 = src1 + 2;
    const bool odd = (t & 1);
    const int ntiles = (r0 >> 3) + 2;
    for (int n0 = 0; n0 < ntiles; ++n0) {
        float d4a[4] = {0.f, 0.f, 0.f, 0.f};
        float d4b[4] = {0.f, 0.f, 0.f, 0.f};
        const int jrow = n0*8 + g;
        #pragma unroll
        for (int k = 0; k < 8; k += 2) {
            mma1688(d4a, qa[k],   Ks[jrow*68 + k*8 + t],     Ks[jrow*68 + k*8 + t + 4]);
            mma1688(d4b, qa[k+1], Ks[jrow*68 + (k+1)*8 + t], Ks[jrow*68 + (k+1)*8 + t + 4]);
        }
        float d4[4];
        #pragma unroll
        for (int i = 0; i < 4; ++i) d4[i] = d4a[i] + d4b[i];

        const int ca = n0*8 + 2*t;
        d4[0] = (ca     <= ra) ? d4[0] : 0.f;
        d4[1] = (ca + 1 <= ra) ? d4[1] : 0.f;
        d4[2] = (ca     <= rb) ? d4[2] : 0.f;
        d4[3] = (ca + 1 <= rb) ? d4[3] : 0.f;
        rs0 += d4[0] + d4[1];
        rs1 += d4[2] + d4[3];

        // C-fragment -> A-fragment conversion via quad shuffles
        const float e0 = __shfl_sync(0xffffffffu, d4[0], src1);
        const float e1 = __shfl_sync(0xffffffffu, d4[1], src1);
        const float e2 = __shfl_sync(0xffffffffu, d4[2], src1);
        const float e3 = __shfl_sync(0xffffffffu, d4[3], src1);
        const float f0 = __shfl_sync(0xffffffffu, d4[0], src2);
        const float f1 = __shfl_sync(0xffffffffu, d4[1], src2);
        const float f2 = __shfl_sync(0xffffffffu, d4[2], src2);
        const float f3 = __shfl_sync(0xffffffffu, d4[3], src2);
        uint32_t sa[4];
        sa[0] = tf32c(odd ? e1 : e0);
        sa[1] = tf32c(odd ? e3 : e2);
        sa[2] = tf32c(odd ? f1 : f0);
        sa[3] = tf32c(odd ? f3 : f2);

        const int j0 = n0*8 + t;
        #pragma unroll
        for (int nv = 0; nv < 8; ++nv)
            mma1688(D[nv], sa, Vs[j0*68 + nv*8 + g], Vs[(j0 + 4)*68 + nv*8 + g]);
    }

    rs0 += __shfl_xor_sync(0xffffffffu, rs0, 1);
    rs0 += __shfl_xor_sync(0xffffffffu, rs0, 2);
    rs1 += __shfl_xor_sync(0xffffffffu, rs1, 1);
    rs1 += __shfl_xor_sync(0xffffffffu, rs1, 2);
    qs0 += __shfl_xor_sync(0xffffffffu, qs0, 1);
    qs0 += __shfl_xor_sync(0xffffffffu, qs0, 2);
    qs1 += __shfl_xor_sync(0xffffffffu, qs1, 1);
    qs1 += __shfl_xor_sync(0xffffffffu, qs1, 2);
    const float inva = 1.f / rs0, invb = 1.f / rs1;
    const float eqa = er * qs0, eqb = er * qs1;

    float* orow_a = out + (tokBase + ra)*DIM;
    float* orow_b = out + (tokBase + rb)*DIM;
    #pragma unroll
    for (int n0 = 0; n0 < 8; ++n0) {
        const float v0 = vsP[n0*8 + 2*t], v1 = vsP[n0*8 + 2*t + 1];
        *(float2*)&orow_a[n0*8 + 2*t] = make_float2(
            (D[n0][0] + eqa*v0)*inva, (D[n0][1] + eqa*v1)*inva);
        *(float2*)&orow_b[n0*8 + 2*t] = make_float2(
            (D[n0][2] + eqb*v0)*invb, (D[n0][3] + eqb*v1)*invb);
    }
}

// ---------------------------------------------------------------------------

extern "C" void kernel_launch(void* const* d_in, const int* in_sizes, int n_in,
                              void* d_out, int out_size) {
    const float* q    = (const float*)d_in[0];
    const float* k    = (const float*)d_in[1];
    const float* v    = (const float*)d_in[2];
    const float* proj = (const float*)d_in[3];
    float* out = (float*)d_out;

    cudaFuncSetAttribute(feat_kernel<true >, cudaFuncAttributeMaxDynamicSharedMemorySize, FEATQ_SMEM);
    cudaFuncSetAttribute(feat_kernel<false>, cudaFuncAttributeMaxDynamicSharedMemorySize, FEATK_SMEM);
    cudaFuncSetAttribute(attn_kernel, cudaFuncAttributeMaxDynamicSharedMemorySize, ATTN_SMEM);

    feat_kernel<true ><<<BH*LEN/128, 256, FEATQ_SMEM>>>(q, proj, v);
    feat_kernel<false><<<BH*LEN/128, 256, FEATK_SMEM>>>(k, proj, v);
    scan_kernel<<<528, 256>>>();
    attn_kernel<<<BH*NC, 256, ATTN_SMEM>>>(v, out);
}

// round 16
// speedup vs baseline: 1.0987x; 1.0987x over previous
#include <cuda_runtime.h>
#include <cstdint>
#include <math.h>

#define BH   32
#define LEN  4096
#define DIM  64
#define MF   64
#define CHK  128
#define NC   (LEN/CHK)     // 32

#define DN     0.35355339059327373f  // 64^-0.25
#define RATIO  0.125f                // 64^-0.5
#define EPSV   1e-4f

// Scratch (device globals: allocation-free rule)
__device__ float g_qp[BH*LEN*MF];      // positive features of q (tf32-rounded)
__device__ float g_kp[BH*LEN*MF];      // t = exp(dash - diag) for k (unstabilized)
__device__ float g_bhmax[BH];          // per-(b,h) max of k dash
__device__ float g_kvt[BH*NC*MF*DIM];  // per-chunk sum t_j*v_j, [bh][c][d][m] -> excl prefix
__device__ float g_ts[BH*NC*MF];       // per-chunk sum t_j -> excl prefix
__device__ float g_vs[BH*NC*DIM];      // per-chunk sum v_j -> excl prefix

// ==================== helpers ====================

__device__ __forceinline__ void atomicMaxFloat(float* addr, float val) {
    int* ia = (int*)addr;
    int old = *ia;
    while (__int_as_float(old) < val) {
        int assumed = old;
        old = atomicCAS(ia, assumed, __float_as_int(val));
        if (old == assumed) break;
    }
}

__device__ __forceinline__ uint32_t tf32c(float f) {
    uint32_t r; asm("cvt.rna.tf32.f32 %0, %1;" : "=r"(r) : "f"(f)); return r;
}
__device__ __forceinline__ void tf32split(float f, uint32_t& hi, uint32_t& lo) {
    hi = tf32c(f);
    lo = tf32c(f - __uint_as_float(hi));
}

// mma.sync m16n8k8 tf32: D += A*B
__device__ __forceinline__ void mma1688(float* d, const uint32_t* a, uint32_t b0, uint32_t b1) {
    asm volatile(
        "mma.sync.aligned.m16n8k8.row.col.f32.tf32.tf32.f32 "
        "{%0,%1,%2,%3}, {%4,%5,%6,%7}, {%8,%9}, {%0,%1,%2,%3};"
        : "+f"(d[0]), "+f"(d[1]), "+f"(d[2]), "+f"(d[3])
        : "r"(a[0]), "r"(a[1]), "r"(a[2]), "r"(a[3]), "r"(b0), "r"(b1));
}

// ---------------------------------------------------------------------------
// Feature kernel: 2-term A-split tf32 mma (X corrected to ~fp32; proj tf32-hi).
// 128 rows = one chunk per block, 256 thr.
// IS_Q: per-row max -> exp -> g_qp (tf32-rounded).
// else: t = exp(dash-diag) -> g_kp AND fused chunk-state phase.
// ---------------------------------------------------------------------------
#define FEATQ_SMEM (128*68*4 + 64*68*4)                // 52224
#define FEATK_SMEM (FEATQ_SMEM + 64*133*4)             // 86272

template<bool IS_Q>
__global__ void __launch_bounds__(256, 2)
feat_kernel(const float* __restrict__ x, const float* __restrict__ proj,
            const float* __restrict__ v) {
    extern __shared__ char fsm[];
    float*    Xs  = (float*)fsm;                       // [row][d] (x * DN)
    uint32_t* Ph  = (uint32_t*)(fsm + 128*68*4);       // [m][d] tf32-hi
    uint32_t* VsT = (uint32_t*)(fsm + FEATQ_SMEM);     // [d][j] tf32 (K only)
    uint32_t* tS  = (uint32_t*)fsm;                    // [m][j] tf32, aliases Xs (K only)

    const int tid = threadIdx.x, wid = tid >> 5, lane = tid & 31;
    const int g = lane >> 2, t = lane & 3;
    const int rowBase = blockIdx.x * 128;
    const int bh = blockIdx.x >> 5;

    if (IS_Q && blockIdx.x == 0 && tid < BH) g_bhmax[tid] = -INFINITY;

    for (int i4 = tid; i4 < 1024; i4 += 256) {
        float4 p = ((const float4*)proj)[i4];
        const int d = i4 >> 4, m0 = (i4 & 15) * 4;
        Ph[(m0+0)*68 + d] = tf32c(p.x);
        Ph[(m0+1)*68 + d] = tf32c(p.y);
        Ph[(m0+2)*68 + d] = tf32c(p.z);
        Ph[(m0+3)*68 + d] = tf32c(p.w);
    }
    {
        const float4* xg = (const float4*)(x + (size_t)rowBase * DIM);
        const float4* vg = (const float4*)(v + (size_t)rowBase * DIM);
        for (int i4 = tid; i4 < 2048; i4 += 256) {
            const int r = i4 >> 4, d0 = (i4 & 15) * 4;
            float4 xv = xg[i4];
            Xs[r*68 + d0 + 0] = xv.x * DN;
            Xs[r*68 + d0 + 1] = xv.y * DN;
            Xs[r*68 + d0 + 2] = xv.z * DN;
            Xs[r*68 + d0 + 3] = xv.w * DN;
            if (!IS_Q) {
                float4 v4 = vg[i4];
                VsT[(d0+0)*133 + r] = tf32c(v4.x);
                VsT[(d0+1)*133 + r] = tf32c(v4.y);
                VsT[(d0+2)*133 + r] = tf32c(v4.z);
                VsT[(d0+3)*133 + r] = tf32c(v4.w);
            }
        }
    }
    __syncthreads();

    const int r0 = wid * 16;
    const int ra = r0 + g, rb = ra + 8;

    float dga = 0.f, dgb = 0.f;
    #pragma unroll
    for (int dd = 0; dd < 16; ++dd) {
        const int d = t*16 + dd;
        const float xa = Xs[ra*68 + d], xb = Xs[rb*68 + d];
        dga += xa*xa; dgb += xb*xb;
    }
    dga += __shfl_xor_sync(0xffffffffu, dga, 1);
    dga += __shfl_xor_sync(0xffffffffu, dga, 2);
    dgb += __shfl_xor_sync(0xffffffffu, dgb, 1);
    dgb += __shfl_xor_sync(0xffffffffu, dgb, 2);
    dga *= 0.5f;
    dgb *= 0.5f;

    uint32_t ah[8][4], al[8][4];
    #pragma unroll
    for (int k = 0; k < 8; ++k) {
        tf32split(Xs[ra*68 + k*8 + t],     ah[k][0], al[k][0]);
        tf32split(Xs[rb*68 + k*8 + t],     ah[k][1], al[k][1]);
        tf32split(Xs[ra*68 + k*8 + t + 4], ah[k][2], al[k][2]);
        tf32split(Xs[rb*68 + k*8 + t + 4], ah[k][3], al[k][3]);
    }
    if (!IS_Q) __syncthreads();   // all warps done reading Xs before tS overwrites it

    float D[8][4] = {};
    #pragma unroll
    for (int n0 = 0; n0 < 8; ++n0) {
        const int nrow = n0*8 + g;
        #pragma unroll
        for (int k = 0; k < 8; ++k) {
            const uint32_t bh0 = Ph[nrow*68 + k*8 + t];
            const uint32_t bh1 = Ph[nrow*68 + k*8 + t + 4];
            mma1688(D[n0], ah[k], bh0, bh1);
            mma1688(D[n0], al[k], bh0, bh1);
        }
    }

    if (IS_Q) {
        float mxa = -INFINITY, mxb = -INFINITY;
        #pragma unroll
        for (int n0 = 0; n0 < 8; ++n0) {
            mxa = fmaxf(mxa, fmaxf(D[n0][0], D[n0][1]));
            mxb = fmaxf(mxb, fmaxf(D[n0][2], D[n0][3]));
        }
        mxa = fmaxf(mxa, __shfl_xor_sync(0xffffffffu, mxa, 1));
        mxa = fmaxf(mxa, __shfl_xor_sync(0xffffffffu, mxa, 2));
        mxb = fmaxf(mxb, __shfl_xor_sync(0xffffffffu, mxb, 1));
        mxb = fmaxf(mxb, __shfl_xor_sync(0xffffffffu, mxb, 2));
        const float suba = dga + mxa, subb = dgb + mxb;
        float* qa = g_qp + (size_t)(rowBase + ra)*MF;
        float* qb = g_qp + (size_t)(rowBase + rb)*MF;
        #pragma unroll
        for (int n0 = 0; n0 < 8; ++n0) {
            *(uint2*)&qa[n0*8 + 2*t] = make_uint2(
                tf32c(RATIO * (__expf(D[n0][0] - suba) + EPSV)),
                tf32c(RATIO * (__expf(D[n0][1] - suba) + EPSV)));
            *(uint2*)&qb[n0*8 + 2*t] = make_uint2(
                tf32c(RATIO * (__expf(D[n0][2] - subb) + EPSV)),
                tf32c(RATIO * (__expf(D[n0][3] - subb) + EPSV)));
        }
    } else {
        float bm = -INFINITY;
        float* ka = g_kp + (size_t)(rowBase + ra)*MF;
        float* kb = g_kp + (size_t)(rowBase + rb)*MF;
        #pragma unroll
        for (int n0 = 0; n0 < 8; ++n0) {
            bm = fmaxf(bm, fmaxf(fmaxf(D[n0][0], D[n0][1]), fmaxf(D[n0][2], D[n0][3])));
            const float t0 = __expf(D[n0][0] - dga), t1 = __expf(D[n0][1] - dga);
            const float t2 = __expf(D[n0][2] - dgb), t3 = __expf(D[n0][3] - dgb);
            *(float2*)&ka[n0*8 + 2*t] = make_float2(t0, t1);
            *(float2*)&kb[n0*8 + 2*t] = make_float2(t2, t3);
            const int m0 = n0*8 + 2*t;
            tS[(m0  )*133 + ra] = tf32c(t0);
            tS[(m0+1)*133 + ra] = tf32c(t1);
            tS[(m0  )*133 + rb] = tf32c(t2);
            tS[(m0+1)*133 + rb] = tf32c(t3);
        }
        #pragma unroll
        for (int off = 16; off; off >>= 1)
            bm = fmaxf(bm, __shfl_xor_sync(0xffffffffu, bm, off));
        if (lane == 0) atomicMaxFloat(&g_bhmax[bh], bm);
        __syncthreads();

        // fused chunk-state phase: kvt = V^T @ t, row sums
        const int dw = wid >> 1, nw = wid & 1;
        const int da = dw*16 + g, db = da + 8;
        float D4[4][4] = {};
        #pragma unroll
        for (int kt = 0; kt < 16; ++kt) {
            uint32_t a[4];
            a[0] = VsT[da*133 + kt*8 + t];
            a[1] = VsT[db*133 + kt*8 + t];
            a[2] = VsT[da*133 + kt*8 + t + 4];
            a[3] = VsT[db*133 + kt*8 + t + 4];
            #pragma unroll
            for (int n0 = 0; n0 < 4; ++n0) {
                const int mrow = nw*32 + n0*8 + g;
                mma1688(D4[n0], a, tS[mrow*133 + kt*8 + t], tS[mrow*133 + kt*8 + t + 4]);
            }
        }
        float* kvb = g_kvt + (size_t)blockIdx.x * MF * DIM;
        #pragma unroll
        for (int n0 = 0; n0 < 4; ++n0) {
            const int m = nw*32 + n0*8 + 2*t;
            *(float2*)&kvb[da*MF + m] = make_float2(D4[n0][0], D4[n0][1]);
            *(float2*)&kvb[db*MF + m] = make_float2(D4[n0][2], D4[n0][3]);
        }
        if (tid < 64) {
            float s = 0.f;
            #pragma unroll 8
            for (int j = 0; j < CHK; ++j) s += __uint_as_float(tS[tid*133 + j]);
            g_ts[(size_t)blockIdx.x * MF + tid] = s;
        } else if (tid < 128) {
            const int d = tid - 64;
            float s = 0.f;
            #pragma unroll 8
            for (int j = 0; j < CHK; ++j) s += __uint_as_float(VsT[d*133 + j]);
            g_vs[(size_t)blockIdx.x * DIM + d] = s;
        }
    }
}

// ---------------------------------------------------------------------------
// Exclusive prefix over 32 chunks (batched MLP=32).
// ---------------------------------------------------------------------------
__global__ void scan_kernel() {
    const int tid = threadIdx.x;
    float* p;
    size_t stride;
    if (blockIdx.x < 512) {
        const int gid = blockIdx.x * 256 + tid;
        p = g_kvt + (size_t)(gid >> 12)*NC*MF*DIM + (gid & 4095);
        stride = MF*DIM;
    } else if (blockIdx.x < 520) {
        const int lid = (blockIdx.x - 512) * 256 + tid;
        p = g_ts + (size_t)(lid >> 6)*NC*MF + (lid & 63);
        stride = MF;
    } else {
        const int lid = (blockIdx.x - 520) * 256 + tid;
        p = g_vs + (size_t)(lid >> 6)*NC*DIM + (lid & 63);
        stride = DIM;
    }
    float vals[NC];
    #pragma unroll
    for (int c = 0; c < NC; ++c) vals[c] = p[(size_t)c*stride];
    float run = 0.f;
    #pragma unroll
    for (int c = 0; c < NC; ++c) { const float tv = vals[c]; vals[c] = run; run += tv; }
    #pragma unroll
    for (int c = 0; c < NC; ++c) p[(size_t)c*stride] = vals[c];
}

// ---------------------------------------------------------------------------
// attn: fused S->SV via in-register fragment conversion, 2 CTAs/SM.
// (R12 version — measured 65.2us best.)
// ---------------------------------------------------------------------------
#define KS_OFF   0
#define VS_OFF   34816
#define KVT_OFF  69632
#define KSUM_OFF 87040
#define VSP_OFF  87296
#define ATTN_SMEM 87552

__global__ void __launch_bounds__(256, 2)
attn_kernel(const float* __restrict__ v, float* __restrict__ out) {
    extern __shared__ char smem[];
    uint32_t* Ks   = (uint32_t*)(smem + KS_OFF);
    uint32_t* Vs   = (uint32_t*)(smem + VS_OFF);
    uint32_t* KVT  = (uint32_t*)(smem + KVT_OFF);
    float*    ksum = (float*)(smem + KSUM_OFF);
    float*    vsP  = (float*)(smem + VSP_OFF);

    const int tid = threadIdx.x, wid = tid >> 5, lane = tid & 31;
    const int g = lane >> 2, t = lane & 3;
    const int bh = blockIdx.x >> 5, c = blockIdx.x & 31;
    const size_t tokBase = (size_t)blockIdx.x * CHK;
    const float cr = RATIO * __expf(-g_bhmax[bh]);
    const float er = RATIO * EPSV;

    const int PERM[8] = {0, 1, 2, 3, 7, 6, 5, 4};
    const int r0 = PERM[wid] * 16;
    const int ra = r0 + g, rb = ra + 8;

    // Q fragments straight from gmem (g_qp already tf32-rounded)
    uint32_t qa[8][4];
    {
        const uint32_t* qrow_a = (const uint32_t*)(g_qp + (tokBase + ra)*MF);
        const uint32_t* qrow_b = (const uint32_t*)(g_qp + (tokBase + rb)*MF);
        #pragma unroll
        for (int k = 0; k < 8; ++k) {
            qa[k][0] = qrow_a[k*8 + t];
            qa[k][1] = qrow_b[k*8 + t];
            qa[k][2] = qrow_a[k*8 + t + 4];
            qa[k][3] = qrow_b[k*8 + t + 4];
        }
    }

    const float4* kpp = (const float4*)(g_kp + tokBase*MF);
    const float4* vpp = (const float4*)(v    + tokBase*DIM);
    const float4* kvp = (const float4*)(g_kvt + (size_t)blockIdx.x*MF*DIM);

    for (int i4 = tid; i4 < 2048; i4 += 256) {
        const int r = i4 >> 4, c0 = (i4 & 15) * 4;
        float4 td = kpp[i4];
        Ks[r*68 + c0 + 0] = tf32c(fmaf(td.x, cr, er));
        Ks[r*68 + c0 + 1] = tf32c(fmaf(td.y, cr, er));
        Ks[r*68 + c0 + 2] = tf32c(fmaf(td.z, cr, er));
        Ks[r*68 + c0 + 3] = tf32c(fmaf(td.w, cr, er));
        float4 v4 = vpp[i4];
        Vs[r*68 + c0 + 0] = tf32c(v4.x);
        Vs[r*68 + c0 + 1] = tf32c(v4.y);
        Vs[r*68 + c0 + 2] = tf32c(v4.z);
        Vs[r*68 + c0 + 3] = tf32c(v4.w);
    }
    for (int i4 = tid; i4 < 1024; i4 += 256) {
        const int d = i4 >> 4, m0 = (i4 & 15) * 4;
        float4 kv4 = kvp[i4];
        KVT[d*68 + m0 + 0] = tf32c(cr * kv4.x);
        KVT[d*68 + m0 + 1] = tf32c(cr * kv4.y);
        KVT[d*68 + m0 + 2] = tf32c(cr * kv4.z);
        KVT[d*68 + m0 + 3] = tf32c(cr * kv4.w);
    }
    if (tid < 64) ksum[tid] = fmaf(cr, g_ts[(size_t)blockIdx.x*MF + tid], er * (128.f * c));
    else if (tid < 128) vsP[tid - 64] = g_vs[(size_t)blockIdx.x*DIM + (tid - 64)];
    __syncthreads();

    // denominator part 2 + row feature-sums from registers
    float rs0 = 0.f, rs1 = 0.f, qs0 = 0.f, qs1 = 0.f;
    #pragma unroll
    for (int k = 0; k < 8; ++k) {
        const float q0 = __uint_as_float(qa[k][0]), q2 = __uint_as_float(qa[k][2]);
        const float q1 = __uint_as_float(qa[k][1]), q3 = __uint_as_float(qa[k][3]);
        rs0 += q0 * ksum[k*8 + t] + q2 * ksum[k*8 + t + 4];
        rs1 += q1 * ksum[k*8 + t] + q3 * ksum[k*8 + t + 4];
        qs0 += q0 + q2;
        qs1 += q1 + q3;
    }

    float D[8][4] = {};
    // inter: D = Q @ (cr * KVT_prev)^T
    #pragma unroll
    for (int n0 = 0; n0 < 8; ++n0) {
        const int drow = n0*8 + g;
        #pragma unroll
        for (int k = 0; k < 8; ++k)
            mma1688(D[n0], qa[k], KVT[drow*68 + k*8 + t], KVT[drow*68 + k*8 + t + 4]);
    }

    // fused S -> SV per causal k-tile; S never hits smem.
    const int src1 = (g << 2) + (t >> 1);
    const int src2 = src1 + 2;
    const bool odd = (t & 1);
    const int ntiles = (r0 >> 3) + 2;
    for (int n0 = 0; n0 < ntiles; ++n0) {
        float d4a[4] = {0.f, 0.f, 0.f, 0.f};
        float d4b[4] = {0.f, 0.f, 0.f, 0.f};
        const int jrow = n0*8 + g;
        #pragma unroll
        for (int k = 0; k < 8; k += 2) {
            mma1688(d4a, qa[k],   Ks[jrow*68 + k*8 + t],     Ks[jrow*68 + k*8 + t + 4]);
            mma1688(d4b, qa[k+1], Ks[jrow*68 + (k+1)*8 + t], Ks[jrow*68 + (k+1)*8 + t + 4]);
        }
        float d4[4];
        #pragma unroll
        for (int i = 0; i < 4; ++i) d4[i] = d4a[i] + d4b[i];

        const int ca = n0*8 + 2*t;
        d4[0] = (ca     <= ra) ? d4[0] : 0.f;
        d4[1] = (ca + 1 <= ra) ? d4[1] : 0.f;
        d4[2] = (ca     <= rb) ? d4[2] : 0.f;
        d4[3] = (ca + 1 <= rb) ? d4[3] : 0.f;
        rs0 += d4[0] + d4[1];
        rs1 += d4[2] + d4[3];

        // C-fragment -> A-fragment conversion via quad shuffles
        const float e0 = __shfl_sync(0xffffffffu, d4[0], src1);
        const float e1 = __shfl_sync(0xffffffffu, d4[1], src1);
        const float e2 = __shfl_sync(0xffffffffu, d4[2], src1);
        const float e3 = __shfl_sync(0xffffffffu, d4[3], src1);
        const float f0 = __shfl_sync(0xffffffffu, d4[0], src2);
        const float f1 = __shfl_sync(0xffffffffu, d4[1], src2);
        const float f2 = __shfl_sync(0xffffffffu, d4[2], src2);
        const float f3 = __shfl_sync(0xffffffffu, d4[3], src2);
        uint32_t sa[4];
        sa[0] = tf32c(odd ? e1 : e0);
        sa[1] = tf32c(odd ? e3 : e2);
        sa[2] = tf32c(odd ? f1 : f0);
        sa[3] = tf32c(odd ? f3 : f2);

        const int j0 = n0*8 + t;
        #pragma unroll
        for (int nv = 0; nv < 8; ++nv)
            mma1688(D[nv], sa, Vs[j0*68 + nv*8 + g], Vs[(j0 + 4)*68 + nv*8 + g]);
    }

    rs0 += __shfl_xor_sync(0xffffffffu, rs0, 1);
    rs0 += __shfl_xor_sync(0xffffffffu, rs0, 2);
    rs1 += __shfl_xor_sync(0xffffffffu, rs1, 1);
    rs1 += __shfl_xor_sync(0xffffffffu, rs1, 2);
    qs0 += __shfl_xor_sync(0xffffffffu, qs0, 1);
    qs0 += __shfl_xor_sync(0xffffffffu, qs0, 2);
    qs1 += __shfl_xor_sync(0xffffffffu, qs1, 1);
    qs1 += __shfl_xor_sync(0xffffffffu, qs1, 2);
    const float inva = 1.f / rs0, invb = 1.f / rs1;
    const float eqa = er * qs0, eqb = er * qs1;

    float* orow_a = out + (tokBase + ra)*DIM;
    float* orow_b = out + (tokBase + rb)*DIM;
    #pragma unroll
    for (int n0 = 0; n0 < 8; ++n0) {
        const float v0 = vsP[n0*8 + 2*t], v1 = vsP[n0*8 + 2*t + 1];
        *(float2*)&orow_a[n0*8 + 2*t] = make_float2(
            (D[n0][0] + eqa*v0)*inva, (D[n0][1] + eqa*v1)*inva);
        *(float2*)&orow_b[n0*8 + 2*t] = make_float2(
            (D[n0][2] + eqb*v0)*invb, (D[n0][3] + eqb*v1)*invb);
    }
}

// ---------------------------------------------------------------------------

extern "C" void kernel_launch(void* const* d_in, const int* in_sizes, int n_in,
                              void* d_out, int out_size) {
    const float* q    = (const float*)d_in[0];
    const float* k    = (const float*)d_in[1];
    const float* v    = (const float*)d_in[2];
    const float* proj = (const float*)d_in[3];
    float* out = (float*)d_out;

    cudaFuncSetAttribute(feat_kernel<true >, cudaFuncAttributeMaxDynamicSharedMemorySize, FEATQ_SMEM);
    cudaFuncSetAttribute(feat_kernel<false>, cudaFuncAttributeMaxDynamicSharedMemorySize, FEATK_SMEM);
    cudaFuncSetAttribute(attn_kernel, cudaFuncAttributeMaxDynamicSharedMemorySize, ATTN_SMEM);

    feat_kernel<true ><<<BH*LEN/128, 256, FEATQ_SMEM>>>(q, proj, v);
    feat_kernel<false><<<BH*LEN/128, 256, FEATK_SMEM>>>(k, proj, v);
    scan_kernel<<<528, 256>>>();
    attn_kernel<<<BH*NC, 256, ATTN_SMEM>>>(v, out);
}

// round 17
// speedup vs baseline: 1.1398x; 1.0374x over previous
#include <cuda_runtime.h>
#include <cstdint>
#include <math.h>

#define BH   32
#define LEN  4096
#define DIM  64
#define MF   64
#define CHK  128
#define NC   (LEN/CHK)     // 32

#define DN     0.35355339059327373f  // 64^-0.25
#define RATIO  0.125f                // 64^-0.5
#define EPSV   1e-4f

// Scratch (device globals: allocation-free rule)
__device__ float g_qp[BH*LEN*MF];      // positive features of q (tf32-rounded)
__device__ float g_kp[BH*LEN*MF];      // t = exp(dash - diag) for k (unstabilized)
__device__ float g_bhmax[BH];          // per-(b,h) max of k dash
__device__ float g_kvt[BH*NC*MF*DIM];  // per-chunk sum t_j*v_j, [bh][c][d][m] -> excl prefix
__device__ float g_ts[BH*NC*MF];       // per-chunk sum t_j -> excl prefix
__device__ float g_vs[BH*NC*DIM];      // per-chunk sum v_j -> excl prefix

// ==================== helpers ====================

__device__ __forceinline__ void atomicMaxFloat(float* addr, float val) {
    int* ia = (int*)addr;
    int old = *ia;
    while (__int_as_float(old) < val) {
        int assumed = old;
        old = atomicCAS(ia, assumed, __float_as_int(val));
        if (old == assumed) break;
    }
}

__device__ __forceinline__ uint32_t tf32c(float f) {
    uint32_t r; asm("cvt.rna.tf32.f32 %0, %1;" : "=r"(r) : "f"(f)); return r;
}

// mma.sync m16n8k8 tf32: D += A*B
__device__ __forceinline__ void mma1688(float* d, const uint32_t* a, uint32_t b0, uint32_t b1) {
    asm volatile(
        "mma.sync.aligned.m16n8k8.row.col.f32.tf32.tf32.f32 "
        "{%0,%1,%2,%3}, {%4,%5,%6,%7}, {%8,%9}, {%0,%1,%2,%3};"
        : "+f"(d[0]), "+f"(d[1]), "+f"(d[2]), "+f"(d[3])
        : "r"(a[0]), "r"(a[1]), "r"(a[2]), "r"(a[3]), "r"(b0), "r"(b1));
}

// ---------------------------------------------------------------------------
// Feature kernel: plain tf32 mma (error dominated by attn's S-rounding).
// 128 rows = one chunk per block, 256 thr.
// IS_Q: per-row max -> exp -> g_qp (tf32-rounded).
// else: t = exp(dash-diag) -> g_kp AND fused chunk-state phase.
// ---------------------------------------------------------------------------
#define FEATQ_SMEM (128*68*4 + 64*68*4)                // 52224
#define FEATK_SMEM (FEATQ_SMEM + 64*133*4)             // 86272

template<bool IS_Q>
__global__ void __launch_bounds__(256, 2)
feat_kernel(const float* __restrict__ x, const float* __restrict__ proj,
            const float* __restrict__ v) {
    extern __shared__ char fsm[];
    float*    Xs  = (float*)fsm;                       // [row][d] (x * DN)
    uint32_t* Ph  = (uint32_t*)(fsm + 128*68*4);       // [m][d] tf32
    uint32_t* VsT = (uint32_t*)(fsm + FEATQ_SMEM);     // [d][j] tf32 (K only)
    uint32_t* tS  = (uint32_t*)fsm;                    // [m][j] tf32, aliases Xs (K only)

    const int tid = threadIdx.x, wid = tid >> 5, lane = tid & 31;
    const int g = lane >> 2, t = lane & 3;
    const int rowBase = blockIdx.x * 128;
    const int bh = blockIdx.x >> 5;

    if (IS_Q && blockIdx.x == 0 && tid < BH) g_bhmax[tid] = -INFINITY;

    for (int i4 = tid; i4 < 1024; i4 += 256) {
        float4 p = ((const float4*)proj)[i4];
        const int d = i4 >> 4, m0 = (i4 & 15) * 4;
        Ph[(m0+0)*68 + d] = tf32c(p.x);
        Ph[(m0+1)*68 + d] = tf32c(p.y);
        Ph[(m0+2)*68 + d] = tf32c(p.z);
        Ph[(m0+3)*68 + d] = tf32c(p.w);
    }
    {
        const float4* xg = (const float4*)(x + (size_t)rowBase * DIM);
        const float4* vg = (const float4*)(v + (size_t)rowBase * DIM);
        for (int i4 = tid; i4 < 2048; i4 += 256) {
            const int r = i4 >> 4, d0 = (i4 & 15) * 4;
            float4 xv = xg[i4];
            Xs[r*68 + d0 + 0] = xv.x * DN;
            Xs[r*68 + d0 + 1] = xv.y * DN;
            Xs[r*68 + d0 + 2] = xv.z * DN;
            Xs[r*68 + d0 + 3] = xv.w * DN;
            if (!IS_Q) {
                float4 v4 = vg[i4];
                VsT[(d0+0)*133 + r] = tf32c(v4.x);
                VsT[(d0+1)*133 + r] = tf32c(v4.y);
                VsT[(d0+2)*133 + r] = tf32c(v4.z);
                VsT[(d0+3)*133 + r] = tf32c(v4.w);
            }
        }
    }
    __syncthreads();

    const int r0 = wid * 16;
    const int ra = r0 + g, rb = ra + 8;

    float dga = 0.f, dgb = 0.f;
    #pragma unroll
    for (int dd = 0; dd < 16; ++dd) {
        const int d = t*16 + dd;
        const float xa = Xs[ra*68 + d], xb = Xs[rb*68 + d];
        dga += xa*xa; dgb += xb*xb;
    }
    dga += __shfl_xor_sync(0xffffffffu, dga, 1);
    dga += __shfl_xor_sync(0xffffffffu, dga, 2);
    dgb += __shfl_xor_sync(0xffffffffu, dgb, 1);
    dgb += __shfl_xor_sync(0xffffffffu, dgb, 2);
    dga *= 0.5f;
    dgb *= 0.5f;

    uint32_t ah[8][4];
    #pragma unroll
    for (int k = 0; k < 8; ++k) {
        ah[k][0] = tf32c(Xs[ra*68 + k*8 + t]);
        ah[k][1] = tf32c(Xs[rb*68 + k*8 + t]);
        ah[k][2] = tf32c(Xs[ra*68 + k*8 + t + 4]);
        ah[k][3] = tf32c(Xs[rb*68 + k*8 + t + 4]);
    }
    if (!IS_Q) __syncthreads();   // all warps done reading Xs before tS overwrites it

    float D[8][4] = {};
    #pragma unroll
    for (int n0 = 0; n0 < 8; ++n0) {
        const int nrow = n0*8 + g;
        #pragma unroll
        for (int k = 0; k < 8; ++k)
            mma1688(D[n0], ah[k], Ph[nrow*68 + k*8 + t], Ph[nrow*68 + k*8 + t + 4]);
    }

    if (IS_Q) {
        float mxa = -INFINITY, mxb = -INFINITY;
        #pragma unroll
        for (int n0 = 0; n0 < 8; ++n0) {
            mxa = fmaxf(mxa, fmaxf(D[n0][0], D[n0][1]));
            mxb = fmaxf(mxb, fmaxf(D[n0][2], D[n0][3]));
        }
        mxa = fmaxf(mxa, __shfl_xor_sync(0xffffffffu, mxa, 1));
        mxa = fmaxf(mxa, __shfl_xor_sync(0xffffffffu, mxa, 2));
        mxb = fmaxf(mxb, __shfl_xor_sync(0xffffffffu, mxb, 1));
        mxb = fmaxf(mxb, __shfl_xor_sync(0xffffffffu, mxb, 2));
        const float suba = dga + mxa, subb = dgb + mxb;
        float* qa = g_qp + (size_t)(rowBase + ra)*MF;
        float* qb = g_qp + (size_t)(rowBase + rb)*MF;
        #pragma unroll
        for (int n0 = 0; n0 < 8; ++n0) {
            *(uint2*)&qa[n0*8 + 2*t] = make_uint2(
                tf32c(RATIO * (__expf(D[n0][0] - suba) + EPSV)),
                tf32c(RATIO * (__expf(D[n0][1] - suba) + EPSV)));
            *(uint2*)&qb[n0*8 + 2*t] = make_uint2(
                tf32c(RATIO * (__expf(D[n0][2] - subb) + EPSV)),
                tf32c(RATIO * (__expf(D[n0][3] - subb) + EPSV)));
        }
    } else {
        float bm = -INFINITY;
        float* ka = g_kp + (size_t)(rowBase + ra)*MF;
        float* kb = g_kp + (size_t)(rowBase + rb)*MF;
        #pragma unroll
        for (int n0 = 0; n0 < 8; ++n0) {
            bm = fmaxf(bm, fmaxf(fmaxf(D[n0][0], D[n0][1]), fmaxf(D[n0][2], D[n0][3])));
            const float t0 = __expf(D[n0][0] - dga), t1 = __expf(D[n0][1] - dga);
            const float t2 = __expf(D[n0][2] - dgb), t3 = __expf(D[n0][3] - dgb);
            *(float2*)&ka[n0*8 + 2*t] = make_float2(t0, t1);
            *(float2*)&kb[n0*8 + 2*t] = make_float2(t2, t3);
            const int m0 = n0*8 + 2*t;
            tS[(m0  )*133 + ra] = tf32c(t0);
            tS[(m0+1)*133 + ra] = tf32c(t1);
            tS[(m0  )*133 + rb] = tf32c(t2);
            tS[(m0+1)*133 + rb] = tf32c(t3);
        }
        #pragma unroll
        for (int off = 16; off; off >>= 1)
            bm = fmaxf(bm, __shfl_xor_sync(0xffffffffu, bm, off));
        if (lane == 0) atomicMaxFloat(&g_bhmax[bh], bm);
        __syncthreads();

        // fused chunk-state phase: kvt = V^T @ t, row sums
        const int dw = wid >> 1, nw = wid & 1;
        const int da = dw*16 + g, db = da + 8;
        float D4[4][4] = {};
        #pragma unroll
        for (int kt = 0; kt < 16; ++kt) {
            uint32_t a[4];
            a[0] = VsT[da*133 + kt*8 + t];
            a[1] = VsT[db*133 + kt*8 + t];
            a[2] = VsT[da*133 + kt*8 + t + 4];
            a[3] = VsT[db*133 + kt*8 + t + 4];
            #pragma unroll
            for (int n0 = 0; n0 < 4; ++n0) {
                const int mrow = nw*32 + n0*8 + g;
                mma1688(D4[n0], a, tS[mrow*133 + kt*8 + t], tS[mrow*133 + kt*8 + t + 4]);
            }
        }
        float* kvb = g_kvt + (size_t)blockIdx.x * MF * DIM;
        #pragma unroll
        for (int n0 = 0; n0 < 4; ++n0) {
            const int m = nw*32 + n0*8 + 2*t;
            *(float2*)&kvb[da*MF + m] = make_float2(D4[n0][0], D4[n0][1]);
            *(float2*)&kvb[db*MF + m] = make_float2(D4[n0][2], D4[n0][3]);
        }
        if (tid < 64) {
            float s = 0.f;
            #pragma unroll 8
            for (int j = 0; j < CHK; ++j) s += __uint_as_float(tS[tid*133 + j]);
            g_ts[(size_t)blockIdx.x * MF + tid] = s;
        } else if (tid < 128) {
            const int d = tid - 64;
            float s = 0.f;
            #pragma unroll 8
            for (int j = 0; j < CHK; ++j) s += __uint_as_float(VsT[d*133 + j]);
            g_vs[(size_t)blockIdx.x * DIM + d] = s;
        }
    }
}

// ---------------------------------------------------------------------------
// Exclusive prefix over 32 chunks (batched MLP=32).
// ---------------------------------------------------------------------------
__global__ void scan_kernel() {
    const int tid = threadIdx.x;
    float* p;
    size_t stride;
    if (blockIdx.x < 512) {
        const int gid = blockIdx.x * 256 + tid;
        p = g_kvt + (size_t)(gid >> 12)*NC*MF*DIM + (gid & 4095);
        stride = MF*DIM;
    } else if (blockIdx.x < 520) {
        const int lid = (blockIdx.x - 512) * 256 + tid;
        p = g_ts + (size_t)(lid >> 6)*NC*MF + (lid & 63);
        stride = MF;
    } else {
        const int lid = (blockIdx.x - 520) * 256 + tid;
        p = g_vs + (size_t)(lid >> 6)*NC*DIM + (lid & 63);
        stride = DIM;
    }
    float vals[NC];
    #pragma unroll
    for (int c = 0; c < NC; ++c) vals[c] = p[(size_t)c*stride];
    float run = 0.f;
    #pragma unroll
    for (int c = 0; c < NC; ++c) { const float tv = vals[c]; vals[c] = run; run += tv; }
    #pragma unroll
    for (int c = 0; c < NC; ++c) p[(size_t)c*stride] = vals[c];
}

// ---------------------------------------------------------------------------
// attn: fused S->SV via in-register fragment conversion, 2 CTAs/SM.
// (R12 version — measured 65.2us best.)
// ---------------------------------------------------------------------------
#define KS_OFF   0
#define VS_OFF   34816
#define KVT_OFF  69632
#define KSUM_OFF 87040
#define VSP_OFF  87296
#define ATTN_SMEM 87552

__global__ void __launch_bounds__(256, 2)
attn_kernel(const float* __restrict__ v, float* __restrict__ out) {
    extern __shared__ char smem[];
    uint32_t* Ks   = (uint32_t*)(smem + KS_OFF);
    uint32_t* Vs   = (uint32_t*)(smem + VS_OFF);
    uint32_t* KVT  = (uint32_t*)(smem + KVT_OFF);
    float*    ksum = (float*)(smem + KSUM_OFF);
    float*    vsP  = (float*)(smem + VSP_OFF);

    const int tid = threadIdx.x, wid = tid >> 5, lane = tid & 31;
    const int g = lane >> 2, t = lane & 3;
    const int bh = blockIdx.x >> 5, c = blockIdx.x & 31;
    const size_t tokBase = (size_t)blockIdx.x * CHK;
    const float cr = RATIO * __expf(-g_bhmax[bh]);
    const float er = RATIO * EPSV;

    const int PERM[8] = {0, 1, 2, 3, 7, 6, 5, 4};
    const int r0 = PERM[wid] * 16;
    const int ra = r0 + g, rb = ra + 8;

    // Q fragments straight from gmem (g_qp already tf32-rounded)
    uint32_t qa[8][4];
    {
        const uint32_t* qrow_a = (const uint32_t*)(g_qp + (tokBase + ra)*MF);
        const uint32_t* qrow_b = (const uint32_t*)(g_qp + (tokBase + rb)*MF);
        #pragma unroll
        for (int k = 0; k < 8; ++k) {
            qa[k][0] = qrow_a[k*8 + t];
            qa[k][1] = qrow_b[k*8 + t];
            qa[k][2] = qrow_a[k*8 + t + 4];
            qa[k][3] = qrow_b[k*8 + t + 4];
        }
    }

    const float4* kpp = (const float4*)(g_kp + tokBase*MF);
    const float4* vpp = (const float4*)(v    + tokBase*DIM);
    const float4* kvp = (const float4*)(g_kvt + (size_t)blockIdx.x*MF*DIM);

    for (int i4 = tid; i4 < 2048; i4 += 256) {
        const int r = i4 >> 4, c0 = (i4 & 15) * 4;
        float4 td = kpp[i4];
        Ks[r*68 + c0 + 0] = tf32c(fmaf(td.x, cr, er));
        Ks[r*68 + c0 + 1] = tf32c(fmaf(td.y, cr, er));
        Ks[r*68 + c0 + 2] = tf32c(fmaf(td.z, cr, er));
        Ks[r*68 + c0 + 3] = tf32c(fmaf(td.w, cr, er));
        float4 v4 = vpp[i4];
        Vs[r*68 + c0 + 0] = tf32c(v4.x);
        Vs[r*68 + c0 + 1] = tf32c(v4.y);
        Vs[r*68 + c0 + 2] = tf32c(v4.z);
        Vs[r*68 + c0 + 3] = tf32c(v4.w);
    }
    for (int i4 = tid; i4 < 1024; i4 += 256) {
        const int d = i4 >> 4, m0 = (i4 & 15) * 4;
        float4 kv4 = kvp[i4];
        KVT[d*68 + m0 + 0] = tf32c(cr * kv4.x);
        KVT[d*68 + m0 + 1] = tf32c(cr * kv4.y);
        KVT[d*68 + m0 + 2] = tf32c(cr * kv4.z);
        KVT[d*68 + m0 + 3] = tf32c(cr * kv4.w);
    }
    if (tid < 64) ksum[tid] = fmaf(cr, g_ts[(size_t)blockIdx.x*MF + tid], er * (128.f * c));
    else if (tid < 128) vsP[tid - 64] = g_vs[(size_t)blockIdx.x*DIM + (tid - 64)];
    __syncthreads();

    // denominator part 2 + row feature-sums from registers
    float rs0 = 0.f, rs1 = 0.f, qs0 = 0.f, qs1 = 0.f;
    #pragma unroll
    for (int k = 0; k < 8; ++k) {
        const float q0 = __uint_as_float(qa[k][0]), q2 = __uint_as_float(qa[k][2]);
        const float q1 = __uint_as_float(qa[k][1]), q3 = __uint_as_float(qa[k][3]);
        rs0 += q0 * ksum[k*8 + t] + q2 * ksum[k*8 + t + 4];
        rs1 += q1 * ksum[k*8 + t] + q3 * ksum[k*8 + t + 4];
        qs0 += q0 + q2;
        qs1 += q1 + q3;
    }

    float D[8][4] = {};
    // inter: D = Q @ (cr * KVT_prev)^T
    #pragma unroll
    for (int n0 = 0; n0 < 8; ++n0) {
        const int drow = n0*8 + g;
        #pragma unroll
        for (int k = 0; k < 8; ++k)
            mma1688(D[n0], qa[k], KVT[drow*68 + k*8 + t], KVT[drow*68 + k*8 + t + 4]);
    }

    // fused S -> SV per causal k-tile; S never hits smem.
    const int src1 = (g << 2) + (t >> 1);
    const int src2 = src1 + 2;
    const bool odd = (t & 1);
    const int ntiles = (r0 >> 3) + 2;
    for (int n0 = 0; n0 < ntiles; ++n0) {
        float d4a[4] = {0.f, 0.f, 0.f, 0.f};
        float d4b[4] = {0.f, 0.f, 0.f, 0.f};
        const int jrow = n0*8 + g;
        #pragma unroll
        for (int k = 0; k < 8; k += 2) {
            mma1688(d4a, qa[k],   Ks[jrow*68 + k*8 + t],     Ks[jrow*68 + k*8 + t + 4]);
            mma1688(d4b, qa[k+1], Ks[jrow*68 + (k+1)*8 + t], Ks[jrow*68 + (k+1)*8 + t + 4]);
        }
        float d4[4];
        #pragma unroll
        for (int i = 0; i < 4; ++i) d4[i] = d4a[i] + d4b[i];

        const int ca = n0*8 + 2*t;
        d4[0] = (ca     <= ra) ? d4[0] : 0.f;
        d4[1] = (ca + 1 <= ra) ? d4[1] : 0.f;
        d4[2] = (ca     <= rb) ? d4[2] : 0.f;
        d4[3] = (ca + 1 <= rb) ? d4[3] : 0.f;
        rs0 += d4[0] + d4[1];
        rs1 += d4[2] + d4[3];

        // C-fragment -> A-fragment conversion via quad shuffles
        const float e0 = __shfl_sync(0xffffffffu, d4[0], src1);
        const float e1 = __shfl_sync(0xffffffffu, d4[1], src1);
        const float e2 = __shfl_sync(0xffffffffu, d4[2], src1);
        const float e3 = __shfl_sync(0xffffffffu, d4[3], src1);
        const float f0 = __shfl_sync(0xffffffffu, d4[0], src2);
        const float f1 = __shfl_sync(0xffffffffu, d4[1], src2);
        const float f2 = __shfl_sync(0xffffffffu, d4[2], src2);
        const float f3 = __shfl_sync(0xffffffffu, d4[3], src2);
        uint32_t sa[4];
        sa[0] = tf32c(odd ? e1 : e0);
        sa[1] = tf32c(odd ? e3 : e2);
        sa[2] = tf32c(odd ? f1 : f0);
        sa[3] = tf32c(odd ? f3 : f2);

        const int j0 = n0*8 + t;
        #pragma unroll
        for (int nv = 0; nv < 8; ++nv)
            mma1688(D[nv], sa, Vs[j0*68 + nv*8 + g], Vs[(j0 + 4)*68 + nv*8 + g]);
    }

    rs0 += __shfl_xor_sync(0xffffffffu, rs0, 1);
    rs0 += __shfl_xor_sync(0xffffffffu, rs0, 2);
    rs1 += __shfl_xor_sync(0xffffffffu, rs1, 1);
    rs1 += __shfl_xor_sync(0xffffffffu, rs1, 2);
    qs0 += __shfl_xor_sync(0xffffffffu, qs0, 1);
    qs0 += __shfl_xor_sync(0xffffffffu, qs0, 2);
    qs1 += __shfl_xor_sync(0xffffffffu, qs1, 1);
    qs1 += __shfl_xor_sync(0xffffffffu, qs1, 2);
    const float inva = 1.f / rs0, invb = 1.f / rs1;
    const float eqa = er * qs0, eqb = er * qs1;

    float* orow_a = out + (tokBase + ra)*DIM;
    float* orow_b = out + (tokBase + rb)*DIM;
    #pragma unroll
    for (int n0 = 0; n0 < 8; ++n0) {
        const float v0 = vsP[n0*8 + 2*t], v1 = vsP[n0*8 + 2*t + 1];
        *(float2*)&orow_a[n0*8 + 2*t] = make_float2(
            (D[n0][0] + eqa*v0)*inva, (D[n0][1] + eqa*v1)*inva);
        *(float2*)&orow_b[n0*8 + 2*t] = make_float2(
            (D[n0][2] + eqb*v0)*invb, (D[n0][3] + eqb*v1)*invb);
    }
}

// ---------------------------------------------------------------------------

extern "C" void kernel_launch(void* const* d_in, const int* in_sizes, int n_in,
                              void* d_out, int out_size) {
    const float* q    = (const float*)d_in[0];
    const float* k    = (const float*)d_in[1];
    const float* v    = (const float*)d_in[2];
    const float* proj = (const float*)d_in[3];
    float* out = (float*)d_out;

    cudaFuncSetAttribute(feat_kernel<true >, cudaFuncAttributeMaxDynamicSharedMemorySize, FEATQ_SMEM);
    cudaFuncSetAttribute(feat_kernel<false>, cudaFuncAttributeMaxDynamicSharedMemorySize, FEATK_SMEM);
    cudaFuncSetAttribute(attn_kernel, cudaFuncAttributeMaxDynamicSharedMemorySize, ATTN_SMEM);

    feat_kernel<true ><<<BH*LEN/128, 256, FEATQ_SMEM>>>(q, proj, v);
    feat_kernel<false><<<BH*LEN/128, 256, FEATK_SMEM>>>(k, proj, v);
    scan_kernel<<<528, 256>>>();
    attn_kernel<<<BH*NC, 256, ATTN_SMEM>>>(v, out);
}